// round 1
// baseline (speedup 1.0000x reference)
#include <cuda_runtime.h>
#include <cuda_bf16.h>

// Problem shape is fixed: [16, 3, 512, 512] fp32 for pred and target.
#define HW      262144          // 512*512
#define HW4     65536           // HW/4 (float4 units per plane)
#define BATCH   16
#define NVEC    (BATCH * HW4)   // 1,048,576 float4 pixel-groups
#define NBLOCKS 1024
#define NTHREADS 256
#define INV_N   (1.0f / 12582912.0f)   // 1 / (16*3*512*512)

__device__ float g_partials[NBLOCKS];

// f(t) from the LAB transform. Both branches computed, predicated select.
// t >= 0 always here (non-negative combos of rgb in [0,1]).
__device__ __forceinline__ float flab(float t) {
    // cube root via MUFU lg2/ex2 (only selected when t > T0, so log is finite there)
    float c   = exp2f(0.333333343f * __log2f(t));
    float lin = 7.787f * t + 0.137931034f;   // 16/116
    return (t > 0.008856f) ? c : lin;
}

// Returns scaled LAB (L/100, (a+128)/255, (b+128)/255)
__device__ __forceinline__ float3 rgb2lab(float r, float g, float b) {
    const float x = (0.412453f / 0.950456f) * r + (0.35758f / 0.950456f) * g + (0.180423f / 0.950456f) * b;
    const float y = 0.212671f * r + 0.71516f * g + 0.072169f * b;
    const float z = (0.019334f / 1.088754f) * r + (0.119193f / 1.088754f) * g + (0.950227f / 1.088754f) * b;
    float fx = flab(x), fy = flab(y), fz = flab(z);
    float L  = (y > 0.008856f) ? (116.0f * fy - 16.0f) : (903.3f * y);
    float a  = 500.0f * (fx - fy);
    float bb = 200.0f * (fy - fz);
    float3 o;
    o.x = L * 0.01f;
    o.y = (a  + 128.0f) * (1.0f / 255.0f);
    o.z = (bb + 128.0f) * (1.0f / 255.0f);
    return o;
}

__device__ __forceinline__ float sqdiff_lane(float pr, float pg, float pb,
                                             float tr, float tg, float tb) {
    float3 p = rgb2lab(pr, pg, pb);
    float3 t = rgb2lab(tr, tg, tb);
    float d0 = p.x - t.x, d1 = p.y - t.y, d2 = p.z - t.z;
    return d0 * d0 + d1 * d1 + d2 * d2;
}

__global__ void __launch_bounds__(NTHREADS)
lab_loss_main(const float* __restrict__ pred, const float* __restrict__ tgt) {
    float acc = 0.0f;

    for (int i = blockIdx.x * NTHREADS + threadIdx.x; i < NVEC;
         i += NBLOCKS * NTHREADS) {
        int b = i >> 16;            // i / HW4
        int q = i & (HW4 - 1);      // i % HW4

        const float4* pbase = reinterpret_cast<const float4*>(pred) + (size_t)b * 3 * HW4;
        const float4* tbase = reinterpret_cast<const float4*>(tgt)  + (size_t)b * 3 * HW4;

        float4 pr = pbase[q];
        float4 pg = pbase[q + HW4];
        float4 pb = pbase[q + 2 * HW4];
        float4 tr = tbase[q];
        float4 tg = tbase[q + HW4];
        float4 tb = tbase[q + 2 * HW4];

        acc += sqdiff_lane(pr.x, pg.x, pb.x, tr.x, tg.x, tb.x);
        acc += sqdiff_lane(pr.y, pg.y, pb.y, tr.y, tg.y, tb.y);
        acc += sqdiff_lane(pr.z, pg.z, pb.z, tr.z, tg.z, tb.z);
        acc += sqdiff_lane(pr.w, pg.w, pb.w, tr.w, tg.w, tb.w);
    }

    // warp reduce
    #pragma unroll
    for (int off = 16; off > 0; off >>= 1)
        acc += __shfl_xor_sync(0xFFFFFFFFu, acc, off);

    __shared__ float s[NTHREADS / 32];
    int lane = threadIdx.x & 31;
    int wid  = threadIdx.x >> 5;
    if (lane == 0) s[wid] = acc;
    __syncthreads();

    if (wid == 0) {
        float v = (lane < NTHREADS / 32) ? s[lane] : 0.0f;
        #pragma unroll
        for (int off = 4; off > 0; off >>= 1)
            v += __shfl_xor_sync(0xFFFFFFFFu, v, off);
        if (lane == 0) g_partials[blockIdx.x] = v;
    }
}

__global__ void __launch_bounds__(1024)
lab_loss_finish(float* __restrict__ out) {
    __shared__ float s[1024];
    float v = g_partials[threadIdx.x];   // NBLOCKS == 1024
    s[threadIdx.x] = v;
    __syncthreads();
    for (int off = 512; off > 0; off >>= 1) {
        if (threadIdx.x < off) s[threadIdx.x] += s[threadIdx.x + off];
        __syncthreads();
    }
    if (threadIdx.x == 0) out[0] = s[0] * INV_N;   // WEIGHT == 1.0
}

extern "C" void kernel_launch(void* const* d_in, const int* in_sizes, int n_in,
                              void* d_out, int out_size) {
    const float* pred = (const float*)d_in[0];
    const float* tgt  = (const float*)d_in[1];
    float* out = (float*)d_out;

    lab_loss_main<<<NBLOCKS, NTHREADS>>>(pred, tgt);
    lab_loss_finish<<<1, 1024>>>(out);
}

// round 2
// speedup vs baseline: 1.0024x; 1.0024x over previous
#include <cuda_runtime.h>
#include <cuda_bf16.h>

// Problem shape is fixed: [16, 3, 512, 512] fp32 for pred and target.
#define HW      262144          // 512*512
#define HW4     65536           // HW/4 (float4 units per plane)
#define BATCH   16
#define NVEC    (BATCH * HW4)   // 1,048,576 float4 pixel-groups
#define NBLOCKS 1024
#define NTHREADS 256
#define INV_N   (1.0f / 12582912.0f)   // 1 / (16*3*512*512)

__device__ float        g_partials[NBLOCKS];
__device__ unsigned int g_count = 0;   // returns to 0 at end of every launch -> graph-replay safe

// f(t) from the LAB transform. Both branches computed, predicated select.
__device__ __forceinline__ float flab(float t) {
    float c   = exp2f(0.333333343f * __log2f(t));   // MUFU lg2 + ex2
    float lin = 7.787f * t + 0.137931034f;          // 16/116
    return (t > 0.008856f) ? c : lin;
}

// Returns scaled LAB (L/100, (a+128)/255, (b+128)/255)
__device__ __forceinline__ float3 rgb2lab(float r, float g, float b) {
    const float x = (0.412453f / 0.950456f) * r + (0.35758f / 0.950456f) * g + (0.180423f / 0.950456f) * b;
    const float y = 0.212671f * r + 0.71516f * g + 0.072169f * b;
    const float z = (0.019334f / 1.088754f) * r + (0.119193f / 1.088754f) * g + (0.950227f / 1.088754f) * b;
    float fx = flab(x), fy = flab(y), fz = flab(z);
    float L  = (y > 0.008856f) ? (116.0f * fy - 16.0f) : (903.3f * y);
    float a  = 500.0f * (fx - fy);
    float bb = 200.0f * (fy - fz);
    float3 o;
    o.x = L * 0.01f;
    o.y = (a  + 128.0f) * (1.0f / 255.0f);
    o.z = (bb + 128.0f) * (1.0f / 255.0f);
    return o;
}

__device__ __forceinline__ float sqdiff_lane(float pr, float pg, float pb,
                                             float tr, float tg, float tb) {
    float3 p = rgb2lab(pr, pg, pb);
    float3 t = rgb2lab(tr, tg, tb);
    float d0 = p.x - t.x, d1 = p.y - t.y, d2 = p.z - t.z;
    return d0 * d0 + d1 * d1 + d2 * d2;
}

__global__ void __launch_bounds__(NTHREADS)
lab_loss_fused(const float* __restrict__ pred, const float* __restrict__ tgt,
               float* __restrict__ out) {
    float acc = 0.0f;

    for (int i = blockIdx.x * NTHREADS + threadIdx.x; i < NVEC;
         i += NBLOCKS * NTHREADS) {
        int b = i >> 16;            // i / HW4
        int q = i & (HW4 - 1);      // i % HW4

        const float4* pbase = reinterpret_cast<const float4*>(pred) + (size_t)b * 3 * HW4;
        const float4* tbase = reinterpret_cast<const float4*>(tgt)  + (size_t)b * 3 * HW4;

        float4 pr = pbase[q];
        float4 pg = pbase[q + HW4];
        float4 pb = pbase[q + 2 * HW4];
        float4 tr = tbase[q];
        float4 tg = tbase[q + HW4];
        float4 tb = tbase[q + 2 * HW4];

        acc += sqdiff_lane(pr.x, pg.x, pb.x, tr.x, tg.x, tb.x);
        acc += sqdiff_lane(pr.y, pg.y, pb.y, tr.y, tg.y, tb.y);
        acc += sqdiff_lane(pr.z, pg.z, pb.z, tr.z, tg.z, tb.z);
        acc += sqdiff_lane(pr.w, pg.w, pb.w, tr.w, tg.w, tb.w);
    }

    // ---- intra-block reduction ----
    #pragma unroll
    for (int off = 16; off > 0; off >>= 1)
        acc += __shfl_xor_sync(0xFFFFFFFFu, acc, off);

    __shared__ float s[NTHREADS / 32];
    __shared__ bool  is_last;
    int lane = threadIdx.x & 31;
    int wid  = threadIdx.x >> 5;
    if (lane == 0) s[wid] = acc;
    __syncthreads();

    if (wid == 0) {
        float v = (lane < NTHREADS / 32) ? s[lane] : 0.0f;
        #pragma unroll
        for (int off = 4; off > 0; off >>= 1)
            v += __shfl_xor_sync(0xFFFFFFFFu, v, off);
        if (lane == 0) {
            g_partials[blockIdx.x] = v;
            __threadfence();                       // make partial visible before counting
            unsigned old = atomicAdd(&g_count, 1u);
            is_last = (old == NBLOCKS - 1);
        }
    }
    __syncthreads();

    // ---- last block finishes: deterministic tree reduce of g_partials ----
    if (is_last) {
        __threadfence();   // acquire: see all blocks' partials
        float v = 0.0f;
        #pragma unroll
        for (int j = 0; j < NBLOCKS / NTHREADS; j++)
            v += g_partials[threadIdx.x + j * NTHREADS];

        #pragma unroll
        for (int off = 16; off > 0; off >>= 1)
            v += __shfl_xor_sync(0xFFFFFFFFu, v, off);

        if (lane == 0) s[wid] = v;
        __syncthreads();
        if (wid == 0) {
            float t = (lane < NTHREADS / 32) ? s[lane] : 0.0f;
            #pragma unroll
            for (int off = 4; off > 0; off >>= 1)
                t += __shfl_xor_sync(0xFFFFFFFFu, t, off);
            if (lane == 0) {
                out[0] = t * INV_N;    // WEIGHT == 1.0
                g_count = 0;           // reset for next graph replay
            }
        }
    }
}

extern "C" void kernel_launch(void* const* d_in, const int* in_sizes, int n_in,
                              void* d_out, int out_size) {
    const float* pred = (const float*)d_in[0];
    const float* tgt  = (const float*)d_in[1];
    float* out = (float*)d_out;

    lab_loss_fused<<<NBLOCKS, NTHREADS>>>(pred, tgt, out);
}

// round 3
// speedup vs baseline: 1.0936x; 1.0910x over previous
#include <cuda_runtime.h>
#include <cuda_bf16.h>

// Fixed shape: [16, 3, 512, 512] fp32 for pred and target.
#define HW4      65536                 // 512*512/4 float4 per plane
#define NBLOCKS  1024                  // 64 blocks per batch image
#define NTHREADS 256
#define INV_N    (1.0f / 12582912.0f)  // 1 / (16*3*512*512)
#define T0       0.008856f

__device__ float        g_partials[NBLOCKS];
__device__ unsigned int g_count = 0;   // returns to 0 every launch -> graph-replay safe

// ---------- packed f32x2 helpers (Blackwell) ----------
typedef unsigned long long u64;

__device__ __forceinline__ u64 pk2(float lo, float hi) {
    u64 r; asm("mov.b64 %0, {%1, %2};" : "=l"(r) : "f"(lo), "f"(hi)); return r;
}
__device__ __forceinline__ void upk2(u64 v, float& lo, float& hi) {
    asm("mov.b64 {%0, %1}, %2;" : "=f"(lo), "=f"(hi) : "l"(v));
}
__device__ __forceinline__ u64 fma2(u64 a, u64 b, u64 c) {
    u64 d; asm("fma.rn.f32x2 %0, %1, %2, %3;" : "=l"(d) : "l"(a), "l"(b), "l"(c)); return d;
}
__device__ __forceinline__ u64 mul2(u64 a, u64 b) {
    u64 d; asm("mul.rn.f32x2 %0, %1, %2;" : "=l"(d) : "l"(a), "l"(b)); return d;
}

// ---------- scalar LAB pieces ----------
__device__ __forceinline__ float flab(float t) {
    float c   = exp2f(0.33333334f * __log2f(t));     // 2x MUFU
    float lin = fmaf(7.787f, t, 0.13793103f);        // 16/116
    return (t > T0) ? c : lin;
}
__device__ __forceinline__ float Lfun(float y, float fy) {
    return (y > T0) ? fmaf(116.0f, fy, -16.0f) : 903.3f * y;
}

// per-pixel squared-diff with folded scales; +128 terms cancel in the diff
__device__ __forceinline__ float px_term(float xp, float yp, float zp,
                                         float xt, float yt, float zt) {
    float fxp = flab(xp), fyp = flab(yp), fzp = flab(zp);
    float fxt = flab(xt), fyt = flab(yt), fzt = flab(zt);
    float dl  = (Lfun(yp, fyp) - Lfun(yt, fyt)) * 0.01f;
    float dfx = fxp - fxt, dfy = fyp - fyt, dfz = fzp - fzt;
    float da  = (dfx - dfy) * (500.0f / 255.0f);
    float db  = (dfy - dfz) * (200.0f / 255.0f);
    return fmaf(dl, dl, fmaf(da, da, db * db));
}

// two pixels (packed rgb for pred & target) -> sum of their squared diffs
__device__ __forceinline__ float pair_term(
    u64 rp, u64 gp, u64 bp, u64 rt, u64 gt, u64 bt,
    u64 KXR2, u64 KXG2, u64 KXB2,
    u64 KYR2, u64 KYG2, u64 KYB2,
    u64 KZR2, u64 KZG2, u64 KZB2)
{
    u64 xp = fma2(rp, KXR2, fma2(gp, KXG2, mul2(bp, KXB2)));
    u64 yp = fma2(rp, KYR2, fma2(gp, KYG2, mul2(bp, KYB2)));
    u64 zp = fma2(rp, KZR2, fma2(gp, KZG2, mul2(bp, KZB2)));
    u64 xt = fma2(rt, KXR2, fma2(gt, KXG2, mul2(bt, KXB2)));
    u64 yt = fma2(rt, KYR2, fma2(gt, KYG2, mul2(bt, KYB2)));
    u64 zt = fma2(rt, KZR2, fma2(gt, KZG2, mul2(bt, KZB2)));

    float xp0, xp1, yp0, yp1, zp0, zp1, xt0, xt1, yt0, yt1, zt0, zt1;
    upk2(xp, xp0, xp1); upk2(yp, yp0, yp1); upk2(zp, zp0, zp1);
    upk2(xt, xt0, xt1); upk2(yt, yt0, yt1); upk2(zt, zt0, zt1);

    return px_term(xp0, yp0, zp0, xt0, yt0, zt0)
         + px_term(xp1, yp1, zp1, xt1, yt1, zt1);
}

__global__ void __launch_bounds__(NTHREADS)
lab_loss_fused(const float* __restrict__ pred, const float* __restrict__ tgt,
               float* __restrict__ out) {
    // LAB matrix with XN/ZN folded in (compile-time folds)
    const float KXR = 0.412453f / 0.950456f, KXG = 0.35758f / 0.950456f, KXB = 0.180423f / 0.950456f;
    const float KYR = 0.212671f,             KYG = 0.71516f,             KYB = 0.072169f;
    const float KZR = 0.019334f / 1.088754f, KZG = 0.119193f / 1.088754f, KZB = 0.950227f / 1.088754f;

    const u64 KXR2 = pk2(KXR, KXR), KXG2 = pk2(KXG, KXG), KXB2 = pk2(KXB, KXB);
    const u64 KYR2 = pk2(KYR, KYR), KYG2 = pk2(KYG, KYG), KYB2 = pk2(KYB, KYB);
    const u64 KZR2 = pk2(KZR, KZR), KZG2 = pk2(KZG, KZG), KZB2 = pk2(KZB, KZB);

    // 64 blocks per batch image: batch is block-constant, 4 iterations exactly.
    const int batch = blockIdx.x >> 6;
    const int q     = ((blockIdx.x & 63) << 8) | threadIdx.x;

    const float4* p = reinterpret_cast<const float4*>(pred) + (size_t)batch * 3 * HW4 + q;
    const float4* t = reinterpret_cast<const float4*>(tgt)  + (size_t)batch * 3 * HW4 + q;

    float acc = 0.0f;

    #pragma unroll
    for (int it = 0; it < 4; ++it, p += 16384, t += 16384) {
        float4 PR = p[0], PG = p[HW4], PB = p[2 * HW4];
        float4 TR = t[0], TG = t[HW4], TB = t[2 * HW4];

        acc += pair_term(pk2(PR.x, PR.y), pk2(PG.x, PG.y), pk2(PB.x, PB.y),
                         pk2(TR.x, TR.y), pk2(TG.x, TG.y), pk2(TB.x, TB.y),
                         KXR2, KXG2, KXB2, KYR2, KYG2, KYB2, KZR2, KZG2, KZB2);
        acc += pair_term(pk2(PR.z, PR.w), pk2(PG.z, PG.w), pk2(PB.z, PB.w),
                         pk2(TR.z, TR.w), pk2(TG.z, TG.w), pk2(TB.z, TB.w),
                         KXR2, KXG2, KXB2, KYR2, KYG2, KYB2, KZR2, KZG2, KZB2);
    }

    // ---- intra-block reduction ----
    #pragma unroll
    for (int off = 16; off > 0; off >>= 1)
        acc += __shfl_xor_sync(0xFFFFFFFFu, acc, off);

    __shared__ float s[NTHREADS / 32];
    __shared__ bool  is_last;
    int lane = threadIdx.x & 31;
    int wid  = threadIdx.x >> 5;
    if (lane == 0) s[wid] = acc;
    __syncthreads();

    if (wid == 0) {
        float v = (lane < NTHREADS / 32) ? s[lane] : 0.0f;
        #pragma unroll
        for (int off = 4; off > 0; off >>= 1)
            v += __shfl_xor_sync(0xFFFFFFFFu, v, off);
        if (lane == 0) {
            g_partials[blockIdx.x] = v;
            __threadfence();
            unsigned old = atomicAdd(&g_count, 1u);
            is_last = (old == NBLOCKS - 1);
        }
    }
    __syncthreads();

    // ---- last block finishes: deterministic tree reduce ----
    if (is_last) {
        __threadfence();
        float v = 0.0f;
        #pragma unroll
        for (int j = 0; j < NBLOCKS / NTHREADS; j++)
            v += g_partials[threadIdx.x + j * NTHREADS];

        #pragma unroll
        for (int off = 16; off > 0; off >>= 1)
            v += __shfl_xor_sync(0xFFFFFFFFu, v, off);

        if (lane == 0) s[wid] = v;
        __syncthreads();
        if (wid == 0) {
            float r = (lane < NTHREADS / 32) ? s[lane] : 0.0f;
            #pragma unroll
            for (int off = 4; off > 0; off >>= 1)
                r += __shfl_xor_sync(0xFFFFFFFFu, r, off);
            if (lane == 0) {
                out[0] = r * INV_N;   // WEIGHT == 1.0
                g_count = 0;          // reset for next graph replay
            }
        }
    }
}

extern "C" void kernel_launch(void* const* d_in, const int* in_sizes, int n_in,
                              void* d_out, int out_size) {
    const float* pred = (const float*)d_in[0];
    const float* tgt  = (const float*)d_in[1];
    float* out = (float*)d_out;

    lab_loss_fused<<<NBLOCKS, NTHREADS>>>(pred, tgt, out);
}